// round 8
// baseline (speedup 1.0000x reference)
#include <cuda_runtime.h>

#define NANG  4
#define NELEM 128
#define NZ    192
#define NX    192
#define NSAMP 2048
#define NPIX  (NZ * NX)

#define PI_F      3.14159265359f
#define HALF_PI_F 1.57079632679f
#define FS_F      20832000.0f
#define C_F       1540.0f
#define FDEMOD_F  5208000.0f
#define FSoC      (FS_F / C_F)

// Scratch (static device global -- no allocation)
__device__ float2 g_iq[NANG * NELEM * NSAMP];   // interleaved (i,q), 8 MB

// ---------------------------------------------------------------------------
// Pass 1: interleave idata/qdata into float2. 2 floats/thread (measured best).
// ---------------------------------------------------------------------------
__global__ __launch_bounds__(256)
void interleave_k(const float* __restrict__ id,
                  const float* __restrict__ qd) {
    int i = (blockIdx.x * blockDim.x + threadIdx.x) * 2;
    float2 a = *(const float2*)(id + i);
    float2 b = *(const float2*)(qd + i);
    *(float4*)(g_iq + i) = make_float4(a.x, b.x, a.y, b.y);
}

// ---------------------------------------------------------------------------
// One element contribution (branchless): lerp gather + exact (pi/2)*delay
// rotation (quadrant from i0&3, MUFU sincos on frac*pi/2). keep=false lanes
// get zero loads -> zero contribution regardless of the trig values.
// ---------------------------------------------------------------------------
__device__ __forceinline__ void contrib(const float2* __restrict__ row,
                                        float delay, bool keep,
                                        float& ai, float& aq) {
    const int   i0   = __float2int_rd(delay);
    const float frac = delay - (float)i0;

    float2 p0 = make_float2(0.0f, 0.0f);
    float2 p1 = make_float2(0.0f, 0.0f);
    const bool v0 = keep & ((unsigned)i0 < (unsigned)NSAMP);
    const bool v1 = keep & ((unsigned)(i0 + 1) < (unsigned)NSAMP);
    if (v0) p0 = __ldg(row + i0);
    if (v1) p1 = __ldg(row + i0 + 1);

    const float ifoc = fmaf(frac, p1.x - p0.x, p0.x);
    const float qfoc = fmaf(frac, p1.y - p0.y, p0.y);

    const float targ = frac * HALF_PI_F;
    const float s0 = __sinf(targ);
    const float c0 = __cosf(targ);
    const int   q  = i0 & 3;
    float ct = (q & 1) ? s0 : c0;
    float st = (q & 1) ? c0 : s0;
    const unsigned negc = (unsigned)((q + 1) & 2) << 30; // negate cos for q in {1,2}
    const unsigned negs = (unsigned)(q & 2) << 30;       // negate sin for q in {2,3}
    ct = __int_as_float(__float_as_int(ct) ^ negc);
    st = __int_as_float(__float_as_int(st) ^ negs);

    ai += ifoc * ct - qfoc * st;
    aq += qfoc * ct + ifoc * st;
}

// ---------------------------------------------------------------------------
// Pass 2: fused DAS. One thread per pixel handles ALL 4 angles: the rx-side
// geometry (vx, keep, rsqrt) is angle-independent and computed once per
// element; 8 gathers per element batch for MLP. Final phi(z) rotation applied
// inline; writes d_out directly (no partial-sum scratch, no reduce pass).
// Warp = 32 consecutive x at fixed z; element bounds warp-uniform.
// ---------------------------------------------------------------------------
__global__ __launch_bounds__(128)
void das_k(const float* __restrict__ grid,
           const float* __restrict__ angles,
           const float* __restrict__ ele,
           const float* __restrict__ tz,
           float* __restrict__ out) {
    __shared__ float sex[NELEM];
    int t = threadIdx.x;                     // 128 threads: tile = 32(x) x 4(z)
    sex[t] = ele[t * 3];                     // ele_pos[e,0] (blockDim == NELEM)
    __syncthreads();

    const int ix = blockIdx.x * 32 + (t & 31);
    const int iz = blockIdx.y * 4  + (t >> 5);
    const int p  = iz * NX + ix;

    const float x = grid[3 * p + 0];
    const float z = grid[3 * p + 2];         // uniform within a warp

    const float ex0 = sex[0];
    const float exN = sex[NELEM - 1];

    float txdel[NANG];
    bool  txapo[NANG];
    #pragma unroll
    for (int a = 0; a < NANG; a++) {
        const float ang = angles[a];
        const float sa = sinf(ang), ca = cosf(ang), ta = tanf(ang);
        txdel[a] = (x * sa + z * ca + tz[a] * C_F) * FSoC;
        const float xproj = x - z * ta;
        txapo[a] = (xproj >= ex0 * 1.2f) && (xproj <= exN * 1.2f);
    }

    float ai0 = 0.f, aq0 = 0.f, ai1 = 0.f, aq1 = 0.f;
    float ai2 = 0.f, aq2 = 0.f, ai3 = 0.f, aq3 = 0.f;

    const bool anyTx = txapo[0] | txapo[1] | txapo[2] | txapo[3];
    if (__any_sync(0xffffffffu, anyTx)) {
        // warp-uniform element range from the warp's x window and z
        const float x_lo = __shfl_sync(0xffffffffu, x, 0);
        const float x_hi = __shfl_sync(0xffffffffu, x, 31);
        const float inv_pitch = 1.0f / (sex[1] - sex[0]);
        const float hz = 0.5f * z;
        int eLo = (int)floorf((x_lo - hz - ex0) * inv_pitch) - 1;
        int eHi = (int)ceilf ((x_hi + hz - ex0) * inv_pitch) + 1;
        eLo = eLo < 0 ? 0 : eLo;
        eHi = eHi > NELEM - 1 ? NELEM - 1 : eHi;

        const float zz = z * z;
        const float2* __restrict__ row = g_iq + (size_t)eLo * NSAMP;

        #pragma unroll 2
        for (int e = eLo; e <= eHi; e++) {
            const float vx  = x - sex[e];           // exact, matches reference
            const bool  kr  = z > 2.0f * fabsf(vx); // rx keep (angle-independent)
            const float r2  = fmaf(vx, vx, zz);
            const float rx  = r2 * rsqrtf(r2) * FSoC;

            contrib(row,                     txdel[0] + rx, kr & txapo[0], ai0, aq0);
            contrib(row + 1 * NELEM * NSAMP, txdel[1] + rx, kr & txapo[1], ai1, aq1);
            contrib(row + 2 * NELEM * NSAMP, txdel[2] + rx, kr & txapo[2], ai2, aq2);
            contrib(row + 3 * NELEM * NSAMP, txdel[3] + rx, kr & txapo[3], ai3, aq3);
            row += NSAMP;
        }
    }

    const float ai = (ai0 + ai1) + (ai2 + ai3);
    const float aq = (aq0 + aq1) + (aq2 + aq3);

    // deferred pixel-constant rotation phi(z) = -4*pi*FDEMOD*z/C (accurate)
    const float phi = (-4.0f * PI_F * FDEMOD_F / C_F) * z;
    float sb, cb;
    sincosf(phi, &sb, &cb);
    out[p]        = ai * cb - aq * sb;   // idas
    out[NPIX + p] = aq * cb + ai * sb;   // qdas
}

extern "C" void kernel_launch(void* const* d_in, const int* in_sizes, int n_in,
                              void* d_out, int out_size) {
    const float* idata  = (const float*)d_in[0];
    const float* qdata  = (const float*)d_in[1];
    const float* grid   = (const float*)d_in[2];
    const float* angles = (const float*)d_in[3];
    const float* ele    = (const float*)d_in[4];
    const float* tz     = (const float*)d_in[5];

    int total = NANG * NELEM * NSAMP;              // 1,048,576
    interleave_k<<<total / (256 * 2), 256>>>(idata, qdata);

    dim3 g(NX / 32, NZ / 4);                       // 6 x 48 = 288 blocks
    das_k<<<g, 128>>>(grid, angles, ele, tz, (float*)d_out);
}

// round 9
// speedup vs baseline: 1.5754x; 1.5754x over previous
#include <cuda_runtime.h>

#define NANG  4
#define NELEM 128
#define NZ    192
#define NX    192
#define NSAMP 2048
#define NPIX  (NZ * NX)

#define PI_F      3.14159265359f
#define HALF_PI_F 1.57079632679f
#define FS_F      20832000.0f
#define C_F       1540.0f
#define FDEMOD_F  5208000.0f
#define FSoC      (FS_F / C_F)

// Scratch (static device globals -- no allocation)
__device__ float2 g_iq[NANG * NELEM * NSAMP];   // interleaved (i,q), 8 MB
__device__ float  g_acc[4][NPIX];               // per-angle-pair partial sums

// ---------------------------------------------------------------------------
// Pass 1: interleave idata/qdata into float2. 2 floats/thread (measured best).
// ---------------------------------------------------------------------------
__global__ __launch_bounds__(256)
void interleave_k(const float* __restrict__ id,
                  const float* __restrict__ qd) {
    int i = (blockIdx.x * blockDim.x + threadIdx.x) * 2;
    float2 a = *(const float2*)(id + i);
    float2 b = *(const float2*)(qd + i);
    *(float4*)(g_iq + i) = make_float4(a.x, b.x, a.y, b.y);
}

// ---------------------------------------------------------------------------
// One element contribution (branchless): lerp gather + exact (pi/2)*delay
// rotation (quadrant from i0&3, MUFU sincos on frac*pi/2). keep=false lanes
// get zero loads -> zero contribution regardless of the trig values.
// ---------------------------------------------------------------------------
__device__ __forceinline__ void contrib(const float2* __restrict__ row,
                                        float delay, bool keep,
                                        float& ai, float& aq) {
    const int   i0   = __float2int_rd(delay);
    const float frac = delay - (float)i0;

    float2 p0 = make_float2(0.0f, 0.0f);
    float2 p1 = make_float2(0.0f, 0.0f);
    const bool v0 = keep & ((unsigned)i0 < (unsigned)NSAMP);
    const bool v1 = keep & ((unsigned)(i0 + 1) < (unsigned)NSAMP);
    if (v0) p0 = __ldg(row + i0);
    if (v1) p1 = __ldg(row + i0 + 1);

    const float ifoc = fmaf(frac, p1.x - p0.x, p0.x);
    const float qfoc = fmaf(frac, p1.y - p0.y, p0.y);

    const float targ = frac * HALF_PI_F;
    const float s0 = __sinf(targ);
    const float c0 = __cosf(targ);
    const int   q  = i0 & 3;
    float ct = (q & 1) ? s0 : c0;
    float st = (q & 1) ? c0 : s0;
    const unsigned negc = (unsigned)((q + 1) & 2) << 30; // negate cos for q in {1,2}
    const unsigned negs = (unsigned)(q & 2) << 30;       // negate sin for q in {2,3}
    ct = __int_as_float(__float_as_int(ct) ^ negc);
    st = __int_as_float(__float_as_int(st) ^ negs);

    ai += ifoc * ct - qfoc * st;
    aq += qfoc * ct + ifoc * st;
}

// ---------------------------------------------------------------------------
// Pass 2: DAS, 2 angles per thread (blockIdx.z selects the pair). The rx-side
// geometry (vx, keep, rsqrt) is shared across the pair; 4 gathers per element
// batch for MLP. 2304 warps (~3.9/SMSP) keep latency hidden (R8 showed
// 2/SMSP starves; R7 showed 7.8/SMSP works).
// Warp = 32 consecutive x at fixed z; element bounds warp-uniform.
// ---------------------------------------------------------------------------
__global__ __launch_bounds__(128)
void das_k(const float* __restrict__ grid,
           const float* __restrict__ angles,
           const float* __restrict__ ele,
           const float* __restrict__ tz) {
    __shared__ float sex[NELEM];
    int t = threadIdx.x;                     // 128 threads: tile = 32(x) x 4(z)
    sex[t] = ele[t * 3];                     // ele_pos[e,0] (blockDim == NELEM)
    __syncthreads();

    const int pair = blockIdx.z;             // 0 -> angles {0,1}, 1 -> {2,3}
    const int a0 = pair * 2;
    const int ix = blockIdx.x * 32 + (t & 31);
    const int iz = blockIdx.y * 4  + (t >> 5);
    const int p  = iz * NX + ix;

    const float x = grid[3 * p + 0];
    const float z = grid[3 * p + 2];         // uniform within a warp

    const float ex0 = sex[0];
    const float exN = sex[NELEM - 1];

    float txdel[2];
    bool  txapo[2];
    #pragma unroll
    for (int k = 0; k < 2; k++) {
        const float ang = angles[a0 + k];
        const float sa = sinf(ang), ca = cosf(ang), ta = tanf(ang);
        txdel[k] = (x * sa + z * ca + tz[a0 + k] * C_F) * FSoC;
        const float xproj = x - z * ta;
        txapo[k] = (xproj >= ex0 * 1.2f) && (xproj <= exN * 1.2f);
    }

    float ai0 = 0.f, aq0 = 0.f, ai1 = 0.f, aq1 = 0.f;

    if (__any_sync(0xffffffffu, txapo[0] | txapo[1])) {
        // warp-uniform element range from the warp's x window and z
        const float x_lo = __shfl_sync(0xffffffffu, x, 0);
        const float x_hi = __shfl_sync(0xffffffffu, x, 31);
        const float inv_pitch = 1.0f / (sex[1] - sex[0]);
        const float hz = 0.5f * z;
        int eLo = (int)floorf((x_lo - hz - ex0) * inv_pitch) - 1;
        int eHi = (int)ceilf ((x_hi + hz - ex0) * inv_pitch) + 1;
        eLo = eLo < 0 ? 0 : eLo;
        eHi = eHi > NELEM - 1 ? NELEM - 1 : eHi;

        const float zz = z * z;
        const float2* __restrict__ row =
            g_iq + ((size_t)a0 * NELEM + eLo) * NSAMP;

        #pragma unroll 4
        for (int e = eLo; e <= eHi; e++) {
            const float vx  = x - sex[e];           // exact, matches reference
            const bool  kr  = z > 2.0f * fabsf(vx); // rx keep (angle-independent)
            const float r2  = fmaf(vx, vx, zz);
            const float rx  = r2 * rsqrtf(r2) * FSoC;

            contrib(row,                 txdel[0] + rx, kr & txapo[0], ai0, aq0);
            contrib(row + NELEM * NSAMP, txdel[1] + rx, kr & txapo[1], ai1, aq1);
            row += NSAMP;
        }
    }

    g_acc[pair * 2 + 0][p] = ai0 + ai1;
    g_acc[pair * 2 + 1][p] = aq0 + aq1;
}

// ---------------------------------------------------------------------------
// Pass 3: sum the 2 pair partials + deferred pixel-constant rotation
// phi(z) = -4*pi*FDEMOD*z/C (accurate sincosf, large argument).
// ---------------------------------------------------------------------------
__global__ void reduce_k(const float* __restrict__ grid,
                         float* __restrict__ out) {
    int p = blockIdx.x * blockDim.x + threadIdx.x;
    if (p >= NPIX) return;
    float ai = g_acc[0][p] + g_acc[2][p];
    float aq = g_acc[1][p] + g_acc[3][p];
    const float z = grid[3 * p + 2];
    const float phi = (-4.0f * PI_F * FDEMOD_F / C_F) * z;
    float sb, cb;
    sincosf(phi, &sb, &cb);
    out[p]        = ai * cb - aq * sb;   // idas
    out[NPIX + p] = aq * cb + ai * sb;   // qdas
}

extern "C" void kernel_launch(void* const* d_in, const int* in_sizes, int n_in,
                              void* d_out, int out_size) {
    const float* idata  = (const float*)d_in[0];
    const float* qdata  = (const float*)d_in[1];
    const float* grid   = (const float*)d_in[2];
    const float* angles = (const float*)d_in[3];
    const float* ele    = (const float*)d_in[4];
    const float* tz     = (const float*)d_in[5];

    int total = NANG * NELEM * NSAMP;              // 1,048,576
    interleave_k<<<total / (256 * 2), 256>>>(idata, qdata);

    dim3 g(NX / 32, NZ / 4, 2);                    // 6 x 48 x 2 = 576 blocks
    das_k<<<g, 128>>>(grid, angles, ele, tz);

    reduce_k<<<(NPIX + 255) / 256, 256>>>(grid, (float*)d_out);
}

// round 11
// speedup vs baseline: 2.3533x; 1.4938x over previous
#include <cuda_runtime.h>
#include <cuda_fp16.h>

#define NANG  4
#define NELEM 128
#define NZ    192
#define NX    192
#define NSAMP 2048
#define NPIX  (NZ * NX)

#define PI_F      3.14159265359f
#define HALF_PI_F 1.57079632679f
#define FS_F      20832000.0f
#define C_F       1540.0f
#define FDEMOD_F  5208000.0f
#define FSoC      (FS_F / C_F)

struct __align__(16) h2x4 { __half2 a, b, c, d; };

// Scratch (static device globals -- no allocation)
__device__ __half2 g_iq[NANG * NELEM * NSAMP];  // (i,q) per sample, fp16, 4 MB
__device__ float   g_acc[NANG * 2][NPIX];       // per-angle partial sums

// ---------------------------------------------------------------------------
// Pass 1: pack idata/qdata into half2. 4 samples/thread, float4 in, 16B out.
// ---------------------------------------------------------------------------
__global__ __launch_bounds__(256)
void interleave_k(const float* __restrict__ id,
                  const float* __restrict__ qd) {
    int i = (blockIdx.x * blockDim.x + threadIdx.x) * 4;
    float4 a = *(const float4*)(id + i);
    float4 b = *(const float4*)(qd + i);
    h2x4 packed;
    packed.a = __floats2half2_rn(a.x, b.x);
    packed.b = __floats2half2_rn(a.y, b.y);
    packed.c = __floats2half2_rn(a.z, b.z);
    packed.d = __floats2half2_rn(a.w, b.w);
    *(h2x4*)(g_iq + i) = packed;
}

// ---------------------------------------------------------------------------
// One element contribution (branchless): fp16 lerp gather (fp32 math) + exact
// (pi/2)*delay rotation (quadrant from i0&3, MUFU sincos on frac*pi/2).
// Single bounds predicate covers both endpoints: delay is in [~93,~1520] for
// this geometry, so the split edge cases of the reference are unreachable.
// ---------------------------------------------------------------------------
__device__ __forceinline__ void contrib(const __half2* __restrict__ row,
                                        float delay, bool keep,
                                        float& ai, float& aq) {
    const int   i0   = __float2int_rd(delay);
    const float frac = delay - (float)i0;

    float2 p0 = make_float2(0.0f, 0.0f);
    float2 p1 = make_float2(0.0f, 0.0f);
    const bool v = keep & ((unsigned)i0 < (unsigned)(NSAMP - 1));
    if (v) {
        p0 = __half22float2(__ldg(row + i0));
        p1 = __half22float2(__ldg(row + i0 + 1));
    }

    const float ifoc = fmaf(frac, p1.x - p0.x, p0.x);
    const float qfoc = fmaf(frac, p1.y - p0.y, p0.y);

    const float targ = frac * HALF_PI_F;
    const float s0 = __sinf(targ);
    const float c0 = __cosf(targ);
    const int   q  = i0 & 3;
    float ct = (q & 1) ? s0 : c0;
    float st = (q & 1) ? c0 : s0;
    const unsigned negc = (unsigned)((q + 1) & 2) << 30; // negate cos for q in {1,2}
    const unsigned negs = (unsigned)(q & 2) << 30;       // negate sin for q in {2,3}
    ct = __int_as_float(__float_as_int(ct) ^ negc);
    st = __int_as_float(__float_as_int(st) ^ negs);

    ai += ifoc * ct - qfoc * st;
    aq += qfoc * ct + ifoc * st;
}

// ---------------------------------------------------------------------------
// Pass 2: main DAS (R7 layout: 1 pixel x 1 angle per thread, 4608 warps).
// Warp = 32 consecutive x at fixed z; element bounds warp-uniform so lanes
// stay lockstep on the same element row (coalesced gathers). vx exact.
// ---------------------------------------------------------------------------
__global__ __launch_bounds__(256)
void das_k(const float* __restrict__ grid,
           const float* __restrict__ angles,
           const float* __restrict__ ele,
           const float* __restrict__ tz) {
    __shared__ float sex[NELEM];
    int t = threadIdx.x;                     // tile = 32(x) x 8(z)
    if (t < NELEM) sex[t] = ele[t * 3];      // ele_pos[e,0]
    __syncthreads();

    const int a  = blockIdx.z;
    const int ix = blockIdx.x * 32 + (t & 31);
    const int iz = blockIdx.y * 8  + (t >> 5);
    const int p  = iz * NX + ix;

    const float x = grid[3 * p + 0];
    const float z = grid[3 * p + 2];         // uniform within a warp

    const float ang = angles[a];
    const float sa = sinf(ang);
    const float ca = cosf(ang);
    const float ta = tanf(ang);

    const float txdel = (x * sa + z * ca + tz[a] * C_F) * FSoC;

    const float ex0 = sex[0];
    const float exN = sex[NELEM - 1];

    const float xproj = x - z * ta;
    const bool txapo = (xproj >= ex0 * 1.2f) && (xproj <= exN * 1.2f);

    float ai = 0.0f, aq = 0.0f;

    if (__any_sync(0xffffffffu, txapo)) {
        // warp-uniform element range from the warp's x window and z
        const float x_lo = __shfl_sync(0xffffffffu, x, 0);
        const float x_hi = __shfl_sync(0xffffffffu, x, 31);
        const float inv_pitch = 1.0f / (sex[1] - sex[0]);
        const float hz = 0.5f * z;
        int eLo = (int)floorf((x_lo - hz - ex0) * inv_pitch) - 1;
        int eHi = (int)ceilf ((x_hi + hz - ex0) * inv_pitch) + 1;
        eLo = eLo < 0 ? 0 : eLo;
        eHi = eHi > NELEM - 1 ? NELEM - 1 : eHi;

        const float zz = z * z;
        const __half2* __restrict__ row =
            g_iq + ((size_t)a * NELEM + eLo) * NSAMP;

        #pragma unroll 8
        for (int e = eLo; e <= eHi; e++) {
            const float vx  = x - sex[e];           // exact, matches reference
            const bool keep = txapo & (z > 2.0f * fabsf(vx));
            const float r2  = fmaf(vx, vx, zz);
            const float delay = fmaf(r2 * rsqrtf(r2), FSoC, txdel);
            contrib(row, delay, keep, ai, aq);
            row += NSAMP;
        }
    }

    g_acc[a * 2 + 0][p] = ai;
    g_acc[a * 2 + 1][p] = aq;
}

// ---------------------------------------------------------------------------
// Pass 3: sum angle partials + deferred pixel-constant rotation
// phi(z) = -4*pi*FDEMOD*z/C (accurate sincosf, large argument).
// ---------------------------------------------------------------------------
__global__ void reduce_k(const float* __restrict__ grid,
                         float* __restrict__ out) {
    int p = blockIdx.x * blockDim.x + threadIdx.x;
    if (p >= NPIX) return;
    float ai = g_acc[0][p] + g_acc[2][p] + g_acc[4][p] + g_acc[6][p];
    float aq = g_acc[1][p] + g_acc[3][p] + g_acc[5][p] + g_acc[7][p];
    const float z = grid[3 * p + 2];
    const float phi = (-4.0f * PI_F * FDEMOD_F / C_F) * z;
    float sb, cb;
    sincosf(phi, &sb, &cb);
    out[p]        = ai * cb - aq * sb;   // idas
    out[NPIX + p] = aq * cb + ai * sb;   // qdas
}

extern "C" void kernel_launch(void* const* d_in, const int* in_sizes, int n_in,
                              void* d_out, int out_size) {
    const float* idata  = (const float*)d_in[0];
    const float* qdata  = (const float*)d_in[1];
    const float* grid   = (const float*)d_in[2];
    const float* angles = (const float*)d_in[3];
    const float* ele    = (const float*)d_in[4];
    const float* tz     = (const float*)d_in[5];

    int total = NANG * NELEM * NSAMP;              // 1,048,576
    interleave_k<<<total / (256 * 4), 256>>>(idata, qdata);

    dim3 g(NX / 32, NZ / 8, NANG);                 // 6 x 24 x 4 = 576 blocks
    das_k<<<g, 256>>>(grid, angles, ele, tz);

    reduce_k<<<(NPIX + 255) / 256, 256>>>(grid, (float*)d_out);
}

// round 12
// speedup vs baseline: 2.5923x; 1.1015x over previous
#include <cuda_runtime.h>
#include <cuda_fp16.h>

#define NANG  4
#define NELEM 128
#define NZ    192
#define NX    192
#define NSAMP 2048
#define NPIX  (NZ * NX)

#define PI_F      3.14159265359f
#define HALF_PI_F 1.57079632679f
#define FS_F      20832000.0f
#define C_F       1540.0f
#define FDEMOD_F  5208000.0f
#define FSoC      (FS_F / C_F)

struct __align__(16) h2x4 { __half2 a, b, c, d; };

// Scratch (static device globals -- no allocation)
__device__ __half2 g_iq[NANG * NELEM * NSAMP];  // (i,q) per sample, fp16, 4 MB
__device__ float   g_acc[NANG * 4][NPIX];       // per-(angle,half) partials

// ---------------------------------------------------------------------------
// Pass 1: pack idata/qdata into half2. 4 samples/thread, float4 in, 16B out.
// ---------------------------------------------------------------------------
__global__ __launch_bounds__(256)
void interleave_k(const float* __restrict__ id,
                  const float* __restrict__ qd) {
    int i = (blockIdx.x * blockDim.x + threadIdx.x) * 4;
    float4 a = *(const float4*)(id + i);
    float4 b = *(const float4*)(qd + i);
    h2x4 packed;
    packed.a = __floats2half2_rn(a.x, b.x);
    packed.b = __floats2half2_rn(a.y, b.y);
    packed.c = __floats2half2_rn(a.z, b.z);
    packed.d = __floats2half2_rn(a.w, b.w);
    *(h2x4*)(g_iq + i) = packed;
}

// ---------------------------------------------------------------------------
// One element contribution (branchless): fp16 lerp gather (fp32 math) + exact
// (pi/2)*delay rotation (quadrant from i0&3, MUFU sincos on frac*pi/2).
// Single bounds predicate covers both endpoints (delay interior for this
// geometry, ~[93,1520]).
// ---------------------------------------------------------------------------
__device__ __forceinline__ void contrib(const __half2* __restrict__ row,
                                        float delay, bool keep,
                                        float& ai, float& aq) {
    const int   i0   = __float2int_rd(delay);
    const float frac = delay - (float)i0;

    float2 p0 = make_float2(0.0f, 0.0f);
    float2 p1 = make_float2(0.0f, 0.0f);
    const bool v = keep & ((unsigned)i0 < (unsigned)(NSAMP - 1));
    if (v) {
        p0 = __half22float2(__ldg(row + i0));
        p1 = __half22float2(__ldg(row + i0 + 1));
    }

    const float ifoc = fmaf(frac, p1.x - p0.x, p0.x);
    const float qfoc = fmaf(frac, p1.y - p0.y, p0.y);

    const float targ = frac * HALF_PI_F;
    const float s0 = __sinf(targ);
    const float c0 = __cosf(targ);
    const int   q  = i0 & 3;
    float ct = (q & 1) ? s0 : c0;
    float st = (q & 1) ? c0 : s0;
    const unsigned negc = (unsigned)((q + 1) & 2) << 30; // negate cos for q in {1,2}
    const unsigned negs = (unsigned)(q & 2) << 30;       // negate sin for q in {2,3}
    ct = __int_as_float(__float_as_int(ct) ^ negc);
    st = __int_as_float(__float_as_int(st) ^ negs);

    ai += ifoc * ct - qfoc * st;
    aq += qfoc * ct + ifoc * st;
}

// ---------------------------------------------------------------------------
// Pass 2: main DAS. TWO threads per (pixel, angle): blockIdx.z = a*2 + half,
// each half sums half of the warp-uniform element range. 9216 warps (~48/SM,
// reg-capped) double the latency cover vs the grid-limited 4608 of R7/R11.
// Warp = 32 consecutive x at fixed z; element bounds warp-uniform; vx exact.
// ---------------------------------------------------------------------------
__global__ __launch_bounds__(256)
void das_k(const float* __restrict__ grid,
           const float* __restrict__ angles,
           const float* __restrict__ ele,
           const float* __restrict__ tz) {
    __shared__ float sex[NELEM];
    int t = threadIdx.x;                     // tile = 32(x) x 8(z)
    if (t < NELEM) sex[t] = ele[t * 3];      // ele_pos[e,0]
    __syncthreads();

    const int a    = blockIdx.z >> 1;
    const int half = blockIdx.z & 1;
    const int ix = blockIdx.x * 32 + (t & 31);
    const int iz = blockIdx.y * 8  + (t >> 5);
    const int p  = iz * NX + ix;

    const float x = grid[3 * p + 0];
    const float z = grid[3 * p + 2];         // uniform within a warp

    const float ang = angles[a];
    const float sa = sinf(ang);
    const float ca = cosf(ang);
    const float ta = tanf(ang);

    const float txdel = (x * sa + z * ca + tz[a] * C_F) * FSoC;

    const float ex0 = sex[0];
    const float exN = sex[NELEM - 1];

    const float xproj = x - z * ta;
    const bool txapo = (xproj >= ex0 * 1.2f) && (xproj <= exN * 1.2f);

    float ai = 0.0f, aq = 0.0f;

    if (__any_sync(0xffffffffu, txapo)) {
        // warp-uniform element range from the warp's x window and z
        const float x_lo = __shfl_sync(0xffffffffu, x, 0);
        const float x_hi = __shfl_sync(0xffffffffu, x, 31);
        const float inv_pitch = 1.0f / (sex[1] - sex[0]);
        const float hz = 0.5f * z;
        int eLo = (int)floorf((x_lo - hz - ex0) * inv_pitch) - 1;
        int eHi = (int)ceilf ((x_hi + hz - ex0) * inv_pitch) + 1;
        eLo = eLo < 0 ? 0 : eLo;
        eHi = eHi > NELEM - 1 ? NELEM - 1 : eHi;

        // split the range across the two halves (warp-uniform)
        const int mid = (eLo + eHi + 1) >> 1;
        const int e0 = half ? mid : eLo;
        const int e1 = half ? eHi : (mid - 1);

        const float zz = z * z;
        const __half2* __restrict__ row =
            g_iq + ((size_t)a * NELEM + e0) * NSAMP;

        #pragma unroll 8
        for (int e = e0; e <= e1; e++) {
            const float vx  = x - sex[e];           // exact, matches reference
            const bool keep = txapo & (z > 2.0f * fabsf(vx));
            const float r2  = fmaf(vx, vx, zz);
            const float delay = fmaf(r2 * rsqrtf(r2), FSoC, txdel);
            contrib(row, delay, keep, ai, aq);
            row += NSAMP;
        }
    }

    g_acc[blockIdx.z * 2 + 0][p] = ai;
    g_acc[blockIdx.z * 2 + 1][p] = aq;
}

// ---------------------------------------------------------------------------
// Pass 3: sum the 8 (angle,half) partials + deferred pixel-constant rotation
// phi(z) = -4*pi*FDEMOD*z/C (accurate sincosf, large argument).
// ---------------------------------------------------------------------------
__global__ void reduce_k(const float* __restrict__ grid,
                         float* __restrict__ out) {
    int p = blockIdx.x * blockDim.x + threadIdx.x;
    if (p >= NPIX) return;
    float ai = 0.0f, aq = 0.0f;
    #pragma unroll
    for (int s = 0; s < NANG * 2; s++) {
        ai += g_acc[s * 2 + 0][p];
        aq += g_acc[s * 2 + 1][p];
    }
    const float z = grid[3 * p + 2];
    const float phi = (-4.0f * PI_F * FDEMOD_F / C_F) * z;
    float sb, cb;
    sincosf(phi, &sb, &cb);
    out[p]        = ai * cb - aq * sb;   // idas
    out[NPIX + p] = aq * cb + ai * sb;   // qdas
}

extern "C" void kernel_launch(void* const* d_in, const int* in_sizes, int n_in,
                              void* d_out, int out_size) {
    const float* idata  = (const float*)d_in[0];
    const float* qdata  = (const float*)d_in[1];
    const float* grid   = (const float*)d_in[2];
    const float* angles = (const float*)d_in[3];
    const float* ele    = (const float*)d_in[4];
    const float* tz     = (const float*)d_in[5];

    int total = NANG * NELEM * NSAMP;              // 1,048,576
    interleave_k<<<total / (256 * 4), 256>>>(idata, qdata);

    dim3 g(NX / 32, NZ / 8, NANG * 2);             // 6 x 24 x 8 = 1152 blocks
    das_k<<<g, 256>>>(grid, angles, ele, tz);

    reduce_k<<<(NPIX + 255) / 256, 256>>>(grid, (float*)d_out);
}

// round 13
// speedup vs baseline: 2.6133x; 1.0081x over previous
#include <cuda_runtime.h>
#include <cuda_fp16.h>

#define NANG  4
#define NELEM 128
#define NZ    192
#define NX    192
#define NSAMP 2048
#define NPIX  (NZ * NX)
#define NTOT  (NANG * NELEM * NSAMP)

#define PI_F      3.14159265359f
#define HALF_PI_F 1.57079632679f
#define FS_F      20832000.0f
#define C_F       1540.0f
#define FDEMOD_F  5208000.0f
#define FSoC      (FS_F / C_F)

// Scratch (static device globals -- no allocation)
// g_pair[s] = ( half2(i[s],q[s]), half2(i[s+1],q[s+1]) ) packed in one float2
// (bit-reinterpreted) so a contrib needs ONE aligned LDG.64.
__device__ float2 g_pair[NTOT];                 // 8 MB
__device__ float  g_acc[NANG * 4][NPIX];        // per-(angle,half) partials

__device__ __forceinline__ unsigned h2bits(float i, float q) {
    __half2 h = __floats2half2_rn(i, q);
    return *reinterpret_cast<unsigned*>(&h);
}

// ---------------------------------------------------------------------------
// Pass 1: build the pair-duplicated fp16 table. 4 pair-entries per thread
// (needs 5 consecutive samples; entry at row end is unused by das, so the
// cross-row garbage there is harmless). Two 16B stores per thread.
// ---------------------------------------------------------------------------
__global__ __launch_bounds__(256)
void interleave_k(const float* __restrict__ id,
                  const float* __restrict__ qd) {
    int s = (blockIdx.x * blockDim.x + threadIdx.x) * 4;
    float4 a = *(const float4*)(id + s);
    float4 b = *(const float4*)(qd + s);
    int s4 = (s + 4 < NTOT) ? s + 4 : NTOT - 1;   // guarded lookahead sample
    float a4 = id[s4];
    float b4 = qd[s4];

    unsigned b0 = h2bits(a.x, b.x);
    unsigned b1 = h2bits(a.y, b.y);
    unsigned b2 = h2bits(a.z, b.z);
    unsigned b3 = h2bits(a.w, b.w);
    unsigned b4u = h2bits(a4, b4);

    *(uint4*)(g_pair + s)     = make_uint4(b0, b1, b1, b2);  // entries s, s+1
    *(uint4*)(g_pair + s + 2) = make_uint4(b2, b3, b3, b4u); // entries s+2, s+3
}

// ---------------------------------------------------------------------------
// One element contribution (branchless): ONE LDG.64 fetches both lerp
// endpoints; fp32 lerp + exact (pi/2)*delay rotation (quadrant from i0&3,
// MUFU sincos on frac*pi/2). Single bounds predicate (delay interior for
// this geometry, ~[93,1520]).
// ---------------------------------------------------------------------------
__device__ __forceinline__ void contrib(const float2* __restrict__ row,
                                        float delay, bool keep,
                                        float& ai, float& aq) {
    const int   i0   = __float2int_rd(delay);
    const float frac = delay - (float)i0;

    float2 raw = make_float2(0.0f, 0.0f);
    const bool v = keep & ((unsigned)i0 < (unsigned)(NSAMP - 1));
    if (v) raw = __ldg(row + i0);
    const float2 p0 = __half22float2(*reinterpret_cast<__half2*>(&raw.x));
    const float2 p1 = __half22float2(*reinterpret_cast<__half2*>(&raw.y));

    const float ifoc = fmaf(frac, p1.x - p0.x, p0.x);
    const float qfoc = fmaf(frac, p1.y - p0.y, p0.y);

    const float targ = frac * HALF_PI_F;
    const float s0 = __sinf(targ);
    const float c0 = __cosf(targ);
    const int   q  = i0 & 3;
    float ct = (q & 1) ? s0 : c0;
    float st = (q & 1) ? c0 : s0;
    const unsigned negc = (unsigned)((q + 1) & 2) << 30; // negate cos for q in {1,2}
    const unsigned negs = (unsigned)(q & 2) << 30;       // negate sin for q in {2,3}
    ct = __int_as_float(__float_as_int(ct) ^ negc);
    st = __int_as_float(__float_as_int(st) ^ negs);

    ai += ifoc * ct - qfoc * st;
    aq += qfoc * ct + ifoc * st;
}

// ---------------------------------------------------------------------------
// Pass 2: main DAS. TWO threads per (pixel, angle): blockIdx.z = a*2 + half,
// each summing half the warp-uniform element range (9216 warps, reg-capped
// ~51/SM). Warp = 32 consecutive x at fixed z; bounds warp-uniform; vx exact.
// ---------------------------------------------------------------------------
__global__ __launch_bounds__(256)
void das_k(const float* __restrict__ grid,
           const float* __restrict__ angles,
           const float* __restrict__ ele,
           const float* __restrict__ tz) {
    __shared__ float sex[NELEM];
    int t = threadIdx.x;                     // tile = 32(x) x 8(z)
    if (t < NELEM) sex[t] = ele[t * 3];      // ele_pos[e,0]
    __syncthreads();

    const int a    = blockIdx.z >> 1;
    const int half = blockIdx.z & 1;
    const int ix = blockIdx.x * 32 + (t & 31);
    const int iz = blockIdx.y * 8  + (t >> 5);
    const int p  = iz * NX + ix;

    const float x = grid[3 * p + 0];
    const float z = grid[3 * p + 2];         // uniform within a warp

    const float ang = angles[a];
    const float sa = sinf(ang);
    const float ca = cosf(ang);
    const float ta = tanf(ang);

    const float txdel = (x * sa + z * ca + tz[a] * C_F) * FSoC;

    const float ex0 = sex[0];
    const float exN = sex[NELEM - 1];

    const float xproj = x - z * ta;
    const bool txapo = (xproj >= ex0 * 1.2f) && (xproj <= exN * 1.2f);

    float ai = 0.0f, aq = 0.0f;

    if (__any_sync(0xffffffffu, txapo)) {
        // warp-uniform element range from the warp's x window and z
        const float x_lo = __shfl_sync(0xffffffffu, x, 0);
        const float x_hi = __shfl_sync(0xffffffffu, x, 31);
        const float inv_pitch = 1.0f / (sex[1] - sex[0]);
        const float hz = 0.5f * z;
        int eLo = (int)floorf((x_lo - hz - ex0) * inv_pitch) - 1;
        int eHi = (int)ceilf ((x_hi + hz - ex0) * inv_pitch) + 1;
        eLo = eLo < 0 ? 0 : eLo;
        eHi = eHi > NELEM - 1 ? NELEM - 1 : eHi;

        // split the range across the two halves (warp-uniform)
        const int mid = (eLo + eHi + 1) >> 1;
        const int e0 = half ? mid : eLo;
        const int e1 = half ? eHi : (mid - 1);

        const float zz = z * z;
        const float2* __restrict__ row =
            g_pair + ((size_t)a * NELEM + e0) * NSAMP;

        #pragma unroll 8
        for (int e = e0; e <= e1; e++) {
            const float vx  = x - sex[e];           // exact, matches reference
            const bool keep = txapo & (z > 2.0f * fabsf(vx));
            const float r2  = fmaf(vx, vx, zz);
            const float delay = fmaf(r2 * rsqrtf(r2), FSoC, txdel);
            contrib(row, delay, keep, ai, aq);
            row += NSAMP;
        }
    }

    g_acc[blockIdx.z * 2 + 0][p] = ai;
    g_acc[blockIdx.z * 2 + 1][p] = aq;
}

// ---------------------------------------------------------------------------
// Pass 3: sum the 8 (angle,half) partials + deferred pixel-constant rotation
// phi(z) = -4*pi*FDEMOD*z/C (accurate sincosf, large argument).
// ---------------------------------------------------------------------------
__global__ void reduce_k(const float* __restrict__ grid,
                         float* __restrict__ out) {
    int p = blockIdx.x * blockDim.x + threadIdx.x;
    if (p >= NPIX) return;
    float ai = 0.0f, aq = 0.0f;
    #pragma unroll
    for (int s = 0; s < NANG * 2; s++) {
        ai += g_acc[s * 2 + 0][p];
        aq += g_acc[s * 2 + 1][p];
    }
    const float z = grid[3 * p + 2];
    const float phi = (-4.0f * PI_F * FDEMOD_F / C_F) * z;
    float sb, cb;
    sincosf(phi, &sb, &cb);
    out[p]        = ai * cb - aq * sb;   // idas
    out[NPIX + p] = aq * cb + ai * sb;   // qdas
}

extern "C" void kernel_launch(void* const* d_in, const int* in_sizes, int n_in,
                              void* d_out, int out_size) {
    const float* idata  = (const float*)d_in[0];
    const float* qdata  = (const float*)d_in[1];
    const float* grid   = (const float*)d_in[2];
    const float* angles = (const float*)d_in[3];
    const float* ele    = (const float*)d_in[4];
    const float* tz     = (const float*)d_in[5];

    interleave_k<<<NTOT / (256 * 4), 256>>>(idata, qdata);

    dim3 g(NX / 32, NZ / 8, NANG * 2);             // 6 x 24 x 8 = 1152 blocks
    das_k<<<g, 256>>>(grid, angles, ele, tz);

    reduce_k<<<(NPIX + 255) / 256, 256>>>(grid, (float*)d_out);
}

// round 14
// speedup vs baseline: 2.8956x; 1.1080x over previous
#include <cuda_runtime.h>
#include <cuda_fp16.h>

#define NANG  4
#define NELEM 128
#define NZ    192
#define NX    192
#define NSAMP 2048
#define NPIX  (NZ * NX)
#define NTOT  (NANG * NELEM * NSAMP)

#define PI_F      3.14159265359f
#define HALF_PI_F 1.57079632679f
#define FS_F      20832000.0f
#define C_F       1540.0f
#define FDEMOD_F  5208000.0f
#define FSoC      (FS_F / C_F)

// Scratch (static device globals -- no allocation)
// g_pair[s] = ( R[s], R[s+1] ) where R[s] = rot((pi/2)*s) . (i[s], q[s]),
// each R a half2, packed so one contrib = ONE aligned LDG.64.
__device__ float2 g_pair[NTOT];                 // 8 MB
__device__ float  g_acc[NANG * 4][NPIX];        // per-(angle,half) partials

__device__ __forceinline__ unsigned h2bits(float i, float q) {
    __half2 h = __floats2half2_rn(i, q);
    return *reinterpret_cast<unsigned*>(&h);
}

// ---------------------------------------------------------------------------
// Pass 1: build the pair-duplicated PRE-ROTATED fp16 table. Each thread owns
// 4 consecutive samples starting at s % 4 == 0, so the integer-phase
// quadrants are exactly 0,1,2,3 (and s+4 is quadrant 0 again):
//   R[s+0] = ( i, q)   R[s+1] = (-q, i)   R[s+2] = (-i,-q)   R[s+3] = ( q,-i)
// Rotation is exact (sign/swap). Entry at a row end is never read by das.
// ---------------------------------------------------------------------------
__global__ __launch_bounds__(256)
void interleave_k(const float* __restrict__ id,
                  const float* __restrict__ qd) {
    int s = (blockIdx.x * blockDim.x + threadIdx.x) * 4;
    float4 a = *(const float4*)(id + s);
    float4 b = *(const float4*)(qd + s);
    int s4 = (s + 4 < NTOT) ? s + 4 : NTOT - 1;   // guarded lookahead sample
    float a4 = id[s4];
    float b4 = qd[s4];

    unsigned r0 = h2bits( a.x,  b.x);   // quadrant 0
    unsigned r1 = h2bits(-b.y,  a.y);   // quadrant 1
    unsigned r2 = h2bits(-a.z, -b.z);   // quadrant 2
    unsigned r3 = h2bits( b.w, -a.w);   // quadrant 3
    unsigned r4 = h2bits( a4,   b4);    // quadrant 0 (s+4)

    *(uint4*)(g_pair + s)     = make_uint4(r0, r1, r1, r2);  // entries s, s+1
    *(uint4*)(g_pair + s + 2) = make_uint4(r2, r3, r3, r4);  // entries s+2, s+3
}

// ---------------------------------------------------------------------------
// One element contribution (branchless): ONE LDG.64 fetches both pre-rotated
// endpoints (P0, P1). The residual rotation is rot((pi/2)*frac) with
// frac in [0,1) -- direct MUFU sincos, NO quadrant logic:
//   contribution = rot(pi/2*f) . [ (1-f)P0 + f*(P1.y, -P1.x) ]
// Single bounds predicate (delay interior for this geometry, ~[93,1520]).
// ---------------------------------------------------------------------------
__device__ __forceinline__ void contrib(const float2* __restrict__ row,
                                        float delay, bool keep,
                                        float& ai, float& aq) {
    const int   i0   = __float2int_rd(delay);
    const float frac = delay - (float)i0;

    float2 raw = make_float2(0.0f, 0.0f);
    const bool v = keep & ((unsigned)i0 < (unsigned)(NSAMP - 1));
    if (v) raw = __ldg(row + i0);
    const float2 P0 = __half22float2(*reinterpret_cast<__half2*>(&raw.x));
    const float2 P1 = __half22float2(*reinterpret_cast<__half2*>(&raw.y));

    const float A = fmaf(frac, P1.y - P0.x, P0.x);   // (1-f)P0.x + f*P1.y
    const float B = fmaf(frac, -P1.x - P0.y, P0.y);  // (1-f)P0.y - f*P1.x

    const float targ = frac * HALF_PI_F;
    const float st = __sinf(targ);
    const float ct = __cosf(targ);

    ai += A * ct - B * st;
    aq += B * ct + A * st;
}

// ---------------------------------------------------------------------------
// Pass 2: main DAS. TWO threads per (pixel, angle): blockIdx.z = a*2 + half,
// each summing half the warp-uniform element range (9216 warps, reg-capped
// ~51/SM). Warp = 32 consecutive x at fixed z; bounds warp-uniform; vx exact.
// ---------------------------------------------------------------------------
__global__ __launch_bounds__(256)
void das_k(const float* __restrict__ grid,
           const float* __restrict__ angles,
           const float* __restrict__ ele,
           const float* __restrict__ tz) {
    __shared__ float sex[NELEM];
    int t = threadIdx.x;                     // tile = 32(x) x 8(z)
    if (t < NELEM) sex[t] = ele[t * 3];      // ele_pos[e,0]
    __syncthreads();

    const int a    = blockIdx.z >> 1;
    const int half = blockIdx.z & 1;
    const int ix = blockIdx.x * 32 + (t & 31);
    const int iz = blockIdx.y * 8  + (t >> 5);
    const int p  = iz * NX + ix;

    const float x = grid[3 * p + 0];
    const float z = grid[3 * p + 2];         // uniform within a warp

    const float ang = angles[a];
    const float sa = sinf(ang);
    const float ca = cosf(ang);
    const float ta = tanf(ang);

    const float txdel = (x * sa + z * ca + tz[a] * C_F) * FSoC;

    const float ex0 = sex[0];
    const float exN = sex[NELEM - 1];

    const float xproj = x - z * ta;
    const bool txapo = (xproj >= ex0 * 1.2f) && (xproj <= exN * 1.2f);

    float ai = 0.0f, aq = 0.0f;

    if (__any_sync(0xffffffffu, txapo)) {
        // warp-uniform element range from the warp's x window and z
        const float x_lo = __shfl_sync(0xffffffffu, x, 0);
        const float x_hi = __shfl_sync(0xffffffffu, x, 31);
        const float inv_pitch = 1.0f / (sex[1] - sex[0]);
        const float hz = 0.5f * z;
        int eLo = (int)floorf((x_lo - hz - ex0) * inv_pitch) - 1;
        int eHi = (int)ceilf ((x_hi + hz - ex0) * inv_pitch) + 1;
        eLo = eLo < 0 ? 0 : eLo;
        eHi = eHi > NELEM - 1 ? NELEM - 1 : eHi;

        // split the range across the two halves (warp-uniform)
        const int mid = (eLo + eHi + 1) >> 1;
        const int e0 = half ? mid : eLo;
        const int e1 = half ? eHi : (mid - 1);

        const float zz = z * z;
        const float2* __restrict__ row =
            g_pair + ((size_t)a * NELEM + e0) * NSAMP;

        #pragma unroll 8
        for (int e = e0; e <= e1; e++) {
            const float vx  = x - sex[e];           // exact, matches reference
            const bool keep = txapo & (z > 2.0f * fabsf(vx));
            const float r2  = fmaf(vx, vx, zz);
            const float delay = fmaf(r2 * rsqrtf(r2), FSoC, txdel);
            contrib(row, delay, keep, ai, aq);
            row += NSAMP;
        }
    }

    g_acc[blockIdx.z * 2 + 0][p] = ai;
    g_acc[blockIdx.z * 2 + 1][p] = aq;
}

// ---------------------------------------------------------------------------
// Pass 3: sum the 8 (angle,half) partials + deferred pixel-constant rotation
// phi(z) = -4*pi*FDEMOD*z/C (accurate sincosf, large argument).
// ---------------------------------------------------------------------------
__global__ void reduce_k(const float* __restrict__ grid,
                         float* __restrict__ out) {
    int p = blockIdx.x * blockDim.x + threadIdx.x;
    if (p >= NPIX) return;
    float ai = 0.0f, aq = 0.0f;
    #pragma unroll
    for (int s = 0; s < NANG * 2; s++) {
        ai += g_acc[s * 2 + 0][p];
        aq += g_acc[s * 2 + 1][p];
    }
    const float z = grid[3 * p + 2];
    const float phi = (-4.0f * PI_F * FDEMOD_F / C_F) * z;
    float sb, cb;
    sincosf(phi, &sb, &cb);
    out[p]        = ai * cb - aq * sb;   // idas
    out[NPIX + p] = aq * cb + ai * sb;   // qdas
}

extern "C" void kernel_launch(void* const* d_in, const int* in_sizes, int n_in,
                              void* d_out, int out_size) {
    const float* idata  = (const float*)d_in[0];
    const float* qdata  = (const float*)d_in[1];
    const float* grid   = (const float*)d_in[2];
    const float* angles = (const float*)d_in[3];
    const float* ele    = (const float*)d_in[4];
    const float* tz     = (const float*)d_in[5];

    interleave_k<<<NTOT / (256 * 4), 256>>>(idata, qdata);

    dim3 g(NX / 32, NZ / 8, NANG * 2);             // 6 x 24 x 8 = 1152 blocks
    das_k<<<g, 256>>>(grid, angles, ele, tz);

    reduce_k<<<(NPIX + 255) / 256, 256>>>(grid, (float*)d_out);
}